// round 14
// baseline (speedup 1.0000x reference)
#include <cuda_runtime.h>

#define D      256
#define H      4
#define DK     64
#define B_CAP  128
#define BCAP   8192   // per-b bucket capacity in global
#define SC_CAP 256    // per-b edges processed (Poisson mean ~8)

// ---------------- scratch (static __device__ — no allocations) ----------------
// d_bcnt starts zeroed (static init) and is re-zeroed by k_attn's tail every call.
__device__ float d_qW[B_CAP * H * D];
__device__ int   d_bcnt[B_CAP];
__device__ int   d_bsrc[B_CAP * BCAP];
__device__ float d_ax[B_CAP * H * D];     // per-b aggregated x (pre-WV)

// ============ K1: fused qW-fold (blocks [0, bn*H)) + edge scan (rest) ============
__global__ void k_front(const float* __restrict__ query,
                        const float* __restrict__ WQ,
                        const float* __restrict__ WK,
                        const int* __restrict__ dst,
                        const int* __restrict__ src,
                        const int* __restrict__ glob,
                        int bn, int ne) {
    int bid = blockIdx.x, t = threadIdx.x;
    int lane = t & 31, warp = t >> 5;

    if (bid < bn * H) {
        // qW[b,h,:] = ((q @ WQ^T)_h) @ WK_h * 0.125
        __shared__ float4 qs4[64];
        __shared__ float  qgh[DK];
        int b = bid / H, h = bid % H;
        if (t < 64) qs4[t] = ((const float4*)query)[b * 64 + t];
        __syncthreads();
        float4 qa = qs4[lane], qb = qs4[lane + 32];
#pragma unroll
        for (int g = 0; g < 2; g++) {
            float v[4];
#pragma unroll
            for (int r = 0; r < 4; r++) {
                int j = warp * 8 + g * 4 + r;
                const float4* wq = (const float4*)WQ + (size_t)(h * DK + j) * 64;
                float4 a = wq[lane], c = wq[lane + 32];
                v[r] = a.x * qa.x + a.y * qa.y + a.z * qa.z + a.w * qa.w
                     + c.x * qb.x + c.y * qb.y + c.z * qb.z + c.w * qb.w;
            }
#pragma unroll
            for (int off = 16; off > 0; off >>= 1) {
#pragma unroll
                for (int r = 0; r < 4; r++) v[r] += __shfl_xor_sync(0xffffffffu, v[r], off);
            }
            if (lane < 4) qgh[warp * 8 + g * 4 + lane] = v[lane];
        }
        __syncthreads();
        float acc = 0.f;
#pragma unroll 16
        for (int j = 0; j < DK; j++) acc += qgh[j] * WK[(size_t)(h * DK + j) * D + t];
        d_qW[(b * H + h) * D + t] = acc * 0.125f;
    } else {
        // scan: bucket edges whose dst is a global node (smem hash of glob ids)
        __shared__ int hk[256];
        __shared__ int hv[256];
        hk[t] = -1;
        __syncthreads();
        if (t < bn) {
            int g = glob[t];
            unsigned slot = ((unsigned)g * 2654435761u) >> 24;
            for (;;) {
                int prev = atomicCAS(&hk[slot & 255], -1, g);
                if (prev == -1) { hv[slot & 255] = t; break; }
                if (prev == g) break;
                slot++;
            }
        }
        __syncthreads();

        int sb = bid - bn * H;
        int base = (sb * 256 + t) * 4;
        if (base >= ne) return;
        int ds[4];
        if (base + 4 <= ne) {
            int4 dv = *(const int4*)(dst + base);
            ds[0] = dv.x; ds[1] = dv.y; ds[2] = dv.z; ds[3] = dv.w;
        } else {
            for (int k = 0; k < 4; k++) ds[k] = (base + k < ne) ? dst[base + k] : -1;
        }
#pragma unroll
        for (int k = 0; k < 4; k++) {
            int g = ds[k];
            if (g < 0) continue;
            unsigned slot = ((unsigned)g * 2654435761u) >> 24;
            int bf = -1;
            for (;;) {
                int kk = hk[slot & 255];
                if (kk == -1) break;
                if (kk == g) { bf = hv[slot & 255]; break; }
                slot++;
            }
            if (bf >= 0) {
                int pos = atomicAdd(&d_bcnt[bf], 1);
                if (pos < BCAP) d_bsrc[bf * BCAP + pos] = src[base + k];
            }
        }
    }
}

// ============ K2: per-b scores + softmax + aggregation -> d_ax. grid bn. ============
__global__ void k_attn(const float* __restrict__ x, float* __restrict__ out) {
    __shared__ float4 qW4[H * 64];        // 4 KB
    __shared__ int    slist[SC_CAP];      // 1 KB
    __shared__ float  sc[SC_CAP * H];     // 4 KB
    int b = blockIdx.x, t = threadIdx.x;
    int lane = t & 31, warp = t >> 5;
    const float4* x4 = (const float4*)x;

    qW4[t] = ((const float4*)d_qW)[b * 256 + t];
    int n = d_bcnt[b];
    if (n > SC_CAP) n = SC_CAP;
    for (int i = t; i < n; i += 256) slist[i] = d_bsrc[b * BCAP + i];
    out[b * D + t] = 0.f;                 // zero output for k_epi's atomics
    __syncthreads();

    // Phase A: warp-per-edge scores (x rows land in L1 for Phase C reuse)
    for (int base = 0; base < n; base += 8) {
        int i = base + warp;
        if (i < n) {
            int s = slist[i];
            float4 xa = x4[(size_t)s * 64 + lane];
            float4 xb = x4[(size_t)s * 64 + 32 + lane];
            float v[H];
#pragma unroll
            for (int h = 0; h < H; h++) {
                float4 qa = qW4[h * 64 + lane], qb = qW4[h * 64 + 32 + lane];
                v[h] = xa.x * qa.x + xa.y * qa.y + xa.z * qa.z + xa.w * qa.w
                     + xb.x * qb.x + xb.y * qb.y + xb.z * qb.z + xb.w * qb.w;
            }
#pragma unroll
            for (int off = 16; off > 0; off >>= 1) {
#pragma unroll
                for (int h = 0; h < H; h++) v[h] += __shfl_xor_sync(0xffffffffu, v[h], off);
            }
            if (lane < H) sc[i * H + lane] = v[lane];
        }
    }
    __syncthreads();

    // Phase B: warp-per-head softmax
    if (warp < H) {
        int h = warp;
        float m = -3.4e38f;
        for (int i = lane; i < n; i += 32) m = fmaxf(m, sc[i * H + h]);
#pragma unroll
        for (int off = 16; off > 0; off >>= 1)
            m = fmaxf(m, __shfl_xor_sync(0xffffffffu, m, off));
        float sum = 0.f;
        for (int i = lane; i < n; i += 32) sum += __expf(sc[i * H + h] - m);
#pragma unroll
        for (int off = 16; off > 0; off >>= 1)
            sum += __shfl_xor_sync(0xffffffffu, sum, off);
        float inv = (sum > 0.f) ? 1.f / sum : 0.f;
        for (int i = lane; i < n; i += 32)
            sc[i * H + h] = __expf(sc[i * H + h] - m) * inv;
    }
    __syncthreads();

    // Phase C: aggregation, thread t = dim d; write ax to global
    {
        float a0 = 0.f, a1 = 0.f, a2 = 0.f, a3 = 0.f;
#pragma unroll 4
        for (int i = 0; i < n; i++) {
            float xv = x[(size_t)slist[i] * D + t];
            a0 += sc[i * H + 0] * xv;
            a1 += sc[i * H + 1] * xv;
            a2 += sc[i * H + 2] * xv;
            a3 += sc[i * H + 3] * xv;
        }
        float* axb = d_ax + b * H * D;
        axb[0 * D + t] = a0; axb[1 * D + t] = a1;
        axb[2 * D + t] = a2; axb[3 * D + t] = a3;
    }

    if (t == 0) d_bcnt[b] = 0;            // reset for next call
}

// ============ K3: epilogue. grid (bn, H). block (b,q): mid quarter + partial out ============
// Quarter q of mid rows [64q, 64q+64) lies entirely in head q, so only ax[b,q,:] is needed.
__global__ void k_epi(const float* __restrict__ WV,
                      const float* __restrict__ WO,
                      float* __restrict__ out) {
    __shared__ float axq[D];      // ax[b, q, :]
    __shared__ float midq[DK];    // mid quarter
    int b = blockIdx.x, q = blockIdx.y, t = threadIdx.x;
    int lane = t & 31, warp = t >> 5;

    axq[t] = d_ax[(b * H + q) * D + t];
    __syncthreads();

    // mid[64q + j] = WV[64q+j, :] . axq   — 8 warps x 8 rows, 4-row ILP batches
    float4 a0 = ((const float4*)axq)[lane];
    float4 a1 = ((const float4*)axq)[lane + 32];
#pragma unroll
    for (int g = 0; g < 2; g++) {
        float v[4];
#pragma unroll
        for (int r = 0; r < 4; r++) {
            int j = warp * 8 + g * 4 + r;
            const float4* wv = (const float4*)WV + (size_t)(q * DK + j) * 64;
            float4 w0 = wv[lane], w1 = wv[lane + 32];
            v[r] = w0.x * a0.x + w0.y * a0.y + w0.z * a0.z + w0.w * a0.w
                 + w1.x * a1.x + w1.y * a1.y + w1.z * a1.z + w1.w * a1.w;
        }
#pragma unroll
        for (int off = 16; off > 0; off >>= 1) {
#pragma unroll
            for (int r = 0; r < 4; r++) v[r] += __shfl_xor_sync(0xffffffffu, v[r], off);
        }
        if (lane < 4) midq[warp * 8 + g * 4 + lane] = v[lane];
    }
    __syncthreads();

    // partial out[b, t] += WO[t, 64q:64q+64] . midq  (thread-per-output-row)
    {
        const float4* wo = (const float4*)(WO + (size_t)t * D + q * DK);
        float acc = 0.f;
#pragma unroll
        for (int k = 0; k < 16; k++) {
            float4 w = wo[k];
            acc += w.x * midq[4 * k] + w.y * midq[4 * k + 1]
                 + w.z * midq[4 * k + 2] + w.w * midq[4 * k + 3];
        }
        atomicAdd(&out[b * D + t], acc);
    }
}

extern "C" void kernel_launch(void* const* d_in, const int* in_sizes, int n_in,
                              void* d_out, int out_size) {
    const float* query = (const float*)d_in[0];
    const float* x     = (const float*)d_in[1];
    const float* WQ    = (const float*)d_in[2];
    const float* WK    = (const float*)d_in[3];
    const float* WV    = (const float*)d_in[4];
    const float* WO    = (const float*)d_in[5];
    const int*   src   = (const int*)d_in[6];   // JAX x64 disabled: stored as int32
    const int*   dst   = (const int*)d_in[7];
    const int*   glob  = (const int*)d_in[8];

    int bn = in_sizes[8];              // 64
    if (bn > B_CAP) bn = B_CAP;
    int ne = in_sizes[6];              // 320000

    int scan_blocks = (ne + 4 * 256 - 1) / (4 * 256);   // 313
    k_front<<<bn * H + scan_blocks, 256>>>(query, WQ, WK, dst, src, glob, bn, ne);
    k_attn<<<bn, 256>>>(x, (float*)d_out);
    dim3 ge(bn, H);
    k_epi<<<ge, 256>>>(WV, WO, (float*)d_out);
}

// round 15
// speedup vs baseline: 1.0471x; 1.0471x over previous
#include <cuda_runtime.h>

#define D      256
#define H      4
#define DK     64
#define B_CAP  128
#define BCAP   8192   // per-b bucket capacity in global
#define SC_CAP 256    // per-b edges processed (Poisson mean ~8)

// ---------------- scratch (static __device__ — no allocations) ----------------
// d_bcnt starts zeroed (static init) and is re-zeroed by k_attn's tail every call.
__device__ float d_qW[B_CAP * H * D];
__device__ int   d_bcnt[B_CAP];
__device__ int   d_bsrc[B_CAP * BCAP];
__device__ float d_ax[B_CAP * H * D];     // per-b aggregated x (pre-WV)

// ============ K1: fused qW-fold (blocks [0, bn*H)) + edge scan (rest) ============
__global__ void k_front(const float* __restrict__ query,
                        const float* __restrict__ WQ,
                        const float* __restrict__ WK,
                        const int* __restrict__ dst,
                        const int* __restrict__ src,
                        const int* __restrict__ glob,
                        int bn, int ne) {
    int bid = blockIdx.x, t = threadIdx.x;
    int lane = t & 31, warp = t >> 5;

    if (bid < bn * H) {
        // qW[b,h,:] = ((q @ WQ^T)_h) @ WK_h * 0.125
        __shared__ float4 qs4[64];
        __shared__ float  qgh[DK];
        int b = bid / H, h = bid % H;
        if (t < 64) qs4[t] = ((const float4*)query)[b * 64 + t];
        __syncthreads();
        float4 qa = qs4[lane], qb = qs4[lane + 32];
#pragma unroll
        for (int g = 0; g < 2; g++) {
            float v[4];
#pragma unroll
            for (int r = 0; r < 4; r++) {
                int j = warp * 8 + g * 4 + r;
                const float4* wq = (const float4*)WQ + (size_t)(h * DK + j) * 64;
                float4 a = wq[lane], c = wq[lane + 32];
                v[r] = a.x * qa.x + a.y * qa.y + a.z * qa.z + a.w * qa.w
                     + c.x * qb.x + c.y * qb.y + c.z * qb.z + c.w * qb.w;
            }
#pragma unroll
            for (int off = 16; off > 0; off >>= 1) {
#pragma unroll
                for (int r = 0; r < 4; r++) v[r] += __shfl_xor_sync(0xffffffffu, v[r], off);
            }
            if (lane < 4) qgh[warp * 8 + g * 4 + lane] = v[lane];
        }
        __syncthreads();
        float acc = 0.f;
#pragma unroll 16
        for (int j = 0; j < DK; j++) acc += qgh[j] * WK[(size_t)(h * DK + j) * D + t];
        d_qW[(b * H + h) * D + t] = acc * 0.125f;
    } else {
        // scan: bucket edges whose dst is a global node (smem hash of glob ids)
        // 8 edges per thread: two independent int4 loads -> 2x MLP on dst fetch.
        __shared__ int hk[256];
        __shared__ int hv[256];
        hk[t] = -1;
        __syncthreads();
        if (t < bn) {
            int g = glob[t];
            unsigned slot = ((unsigned)g * 2654435761u) >> 24;
            for (;;) {
                int prev = atomicCAS(&hk[slot & 255], -1, g);
                if (prev == -1) { hv[slot & 255] = t; break; }
                if (prev == g) break;
                slot++;
            }
        }
        __syncthreads();

        int sb = bid - bn * H;
        int base = (sb * 256 + t) * 8;
        if (base >= ne) return;
        int ds[8];
        if (base + 8 <= ne) {
            int4 dv0 = *(const int4*)(dst + base);
            int4 dv1 = *(const int4*)(dst + base + 4);
            ds[0] = dv0.x; ds[1] = dv0.y; ds[2] = dv0.z; ds[3] = dv0.w;
            ds[4] = dv1.x; ds[5] = dv1.y; ds[6] = dv1.z; ds[7] = dv1.w;
        } else {
            for (int k = 0; k < 8; k++) ds[k] = (base + k < ne) ? dst[base + k] : -1;
        }
#pragma unroll
        for (int k = 0; k < 8; k++) {
            int g = ds[k];
            if (g < 0) continue;
            unsigned slot = ((unsigned)g * 2654435761u) >> 24;
            int bf = -1;
            for (;;) {
                int kk = hk[slot & 255];
                if (kk == -1) break;
                if (kk == g) { bf = hv[slot & 255]; break; }
                slot++;
            }
            if (bf >= 0) {
                int pos = atomicAdd(&d_bcnt[bf], 1);
                if (pos < BCAP) d_bsrc[bf * BCAP + pos] = src[base + k];
            }
        }
    }
}

// ============ K2: per-b scores + softmax + aggregation -> d_ax. grid bn. ============
__global__ void k_attn(const float* __restrict__ x, float* __restrict__ out) {
    __shared__ float4 qW4[H * 64];        // 4 KB
    __shared__ int    slist[SC_CAP];      // 1 KB
    __shared__ float  sc[SC_CAP * H];     // 4 KB
    int b = blockIdx.x, t = threadIdx.x;
    int lane = t & 31, warp = t >> 5;
    const float4* x4 = (const float4*)x;

    qW4[t] = ((const float4*)d_qW)[b * 256 + t];
    int n = d_bcnt[b];
    if (n > SC_CAP) n = SC_CAP;
    for (int i = t; i < n; i += 256) slist[i] = d_bsrc[b * BCAP + i];
    out[b * D + t] = 0.f;                 // zero output for k_epi's atomics
    __syncthreads();

    // Phase A: warp-per-edge scores (x rows land in L1 for Phase C reuse)
    for (int base = 0; base < n; base += 8) {
        int i = base + warp;
        if (i < n) {
            int s = slist[i];
            float4 xa = x4[(size_t)s * 64 + lane];
            float4 xb = x4[(size_t)s * 64 + 32 + lane];
            float v[H];
#pragma unroll
            for (int h = 0; h < H; h++) {
                float4 qa = qW4[h * 64 + lane], qb = qW4[h * 64 + 32 + lane];
                v[h] = xa.x * qa.x + xa.y * qa.y + xa.z * qa.z + xa.w * qa.w
                     + xb.x * qb.x + xb.y * qb.y + xb.z * qb.z + xb.w * qb.w;
            }
#pragma unroll
            for (int off = 16; off > 0; off >>= 1) {
#pragma unroll
                for (int h = 0; h < H; h++) v[h] += __shfl_xor_sync(0xffffffffu, v[h], off);
            }
            if (lane < H) sc[i * H + lane] = v[lane];
        }
    }
    __syncthreads();

    // Phase B: warp-per-head softmax
    if (warp < H) {
        int h = warp;
        float m = -3.4e38f;
        for (int i = lane; i < n; i += 32) m = fmaxf(m, sc[i * H + h]);
#pragma unroll
        for (int off = 16; off > 0; off >>= 1)
            m = fmaxf(m, __shfl_xor_sync(0xffffffffu, m, off));
        float sum = 0.f;
        for (int i = lane; i < n; i += 32) sum += __expf(sc[i * H + h] - m);
#pragma unroll
        for (int off = 16; off > 0; off >>= 1)
            sum += __shfl_xor_sync(0xffffffffu, sum, off);
        float inv = (sum > 0.f) ? 1.f / sum : 0.f;
        for (int i = lane; i < n; i += 32)
            sc[i * H + h] = __expf(sc[i * H + h] - m) * inv;
    }
    __syncthreads();

    // Phase C: aggregation, thread t = dim d; write ax to global
    {
        float a0 = 0.f, a1 = 0.f, a2 = 0.f, a3 = 0.f;
#pragma unroll 4
        for (int i = 0; i < n; i++) {
            float xv = x[(size_t)slist[i] * D + t];
            a0 += sc[i * H + 0] * xv;
            a1 += sc[i * H + 1] * xv;
            a2 += sc[i * H + 2] * xv;
            a3 += sc[i * H + 3] * xv;
        }
        float* axb = d_ax + b * H * D;
        axb[0 * D + t] = a0; axb[1 * D + t] = a1;
        axb[2 * D + t] = a2; axb[3 * D + t] = a3;
    }

    if (t == 0) d_bcnt[b] = 0;            // reset for next call
}

// ============ K3: epilogue. grid (bn, H). block (b,q): mid quarter + partial out ============
// Quarter q of mid rows [64q, 64q+64) lies entirely in head q, so only ax[b,q,:] is needed.
__global__ void k_epi(const float* __restrict__ WV,
                      const float* __restrict__ WO,
                      float* __restrict__ out) {
    __shared__ float axq[D];      // ax[b, q, :]
    __shared__ float midq[DK];    // mid quarter
    int b = blockIdx.x, q = blockIdx.y, t = threadIdx.x;
    int lane = t & 31, warp = t >> 5;

    axq[t] = d_ax[(b * H + q) * D + t];
    __syncthreads();

    // mid[64q + j] = WV[64q+j, :] . axq   — 8 warps x 8 rows, 4-row ILP batches
    float4 a0 = ((const float4*)axq)[lane];
    float4 a1 = ((const float4*)axq)[lane + 32];
#pragma unroll
    for (int g = 0; g < 2; g++) {
        float v[4];
#pragma unroll
        for (int r = 0; r < 4; r++) {
            int j = warp * 8 + g * 4 + r;
            const float4* wv = (const float4*)WV + (size_t)(q * DK + j) * 64;
            float4 w0 = wv[lane], w1 = wv[lane + 32];
            v[r] = w0.x * a0.x + w0.y * a0.y + w0.z * a0.z + w0.w * a0.w
                 + w1.x * a1.x + w1.y * a1.y + w1.z * a1.z + w1.w * a1.w;
        }
#pragma unroll
        for (int off = 16; off > 0; off >>= 1) {
#pragma unroll
            for (int r = 0; r < 4; r++) v[r] += __shfl_xor_sync(0xffffffffu, v[r], off);
        }
        if (lane < 4) midq[warp * 8 + g * 4 + lane] = v[lane];
    }
    __syncthreads();

    // partial out[b, t] += WO[t, 64q:64q+64] . midq  (thread-per-output-row)
    {
        const float4* wo = (const float4*)(WO + (size_t)t * D + q * DK);
        float acc = 0.f;
#pragma unroll
        for (int k = 0; k < 16; k++) {
            float4 w = wo[k];
            acc += w.x * midq[4 * k] + w.y * midq[4 * k + 1]
                 + w.z * midq[4 * k + 2] + w.w * midq[4 * k + 3];
        }
        atomicAdd(&out[b * D + t], acc);
    }
}

extern "C" void kernel_launch(void* const* d_in, const int* in_sizes, int n_in,
                              void* d_out, int out_size) {
    const float* query = (const float*)d_in[0];
    const float* x     = (const float*)d_in[1];
    const float* WQ    = (const float*)d_in[2];
    const float* WK    = (const float*)d_in[3];
    const float* WV    = (const float*)d_in[4];
    const float* WO    = (const float*)d_in[5];
    const int*   src   = (const int*)d_in[6];   // JAX x64 disabled: stored as int32
    const int*   dst   = (const int*)d_in[7];
    const int*   glob  = (const int*)d_in[8];

    int bn = in_sizes[8];              // 64
    if (bn > B_CAP) bn = B_CAP;
    int ne = in_sizes[6];              // 320000

    int scan_blocks = (ne + 8 * 256 - 1) / (8 * 256);   // 157
    k_front<<<bn * H + scan_blocks, 256>>>(query, WQ, WK, dst, src, glob, bn, ne);
    k_attn<<<bn, 256>>>(x, (float*)d_out);
    dim3 ge(bn, H);
    k_epi<<<ge, 256>>>(WV, WO, (float*)d_out);
}

// round 16
// speedup vs baseline: 1.0525x; 1.0051x over previous
#include <cuda_runtime.h>

#define D      256
#define H      4
#define DK     64
#define B_CAP  128
#define BCAP   8192   // per-b bucket capacity in global
#define SC_CAP 256    // per-b edges processed (Poisson mean ~8)

// ---------------- scratch (static __device__ — no allocations) ----------------
// d_bcnt starts zeroed (static init) and is re-zeroed by k_attn's tail every call.
__device__ float d_qW[B_CAP * H * D];
__device__ int   d_bcnt[B_CAP];
__device__ int   d_bsrc[B_CAP * BCAP];
__device__ float d_ax[B_CAP * H * D];     // per-b aggregated x (pre-WV)

// ============ K1: fused qW-fold (blocks [0, bn*H)) + edge scan (rest) ============
__global__ void k_front(const float* __restrict__ query,
                        const float* __restrict__ WQ,
                        const float* __restrict__ WK,
                        const int* __restrict__ dst,
                        const int* __restrict__ src,
                        const int* __restrict__ glob,
                        int bn, int ne) {
    int bid = blockIdx.x, t = threadIdx.x;
    int lane = t & 31, warp = t >> 5;

    if (bid < bn * H) {
        // qW[b,h,:] = ((q @ WQ^T)_h) @ WK_h * 0.125
        __shared__ float4 qs4[64];
        __shared__ float  qgh[DK];
        int b = bid / H, h = bid % H;
        if (t < 64) qs4[t] = ((const float4*)query)[b * 64 + t];
        __syncthreads();
        float4 qa = qs4[lane], qb = qs4[lane + 32];
#pragma unroll
        for (int g = 0; g < 2; g++) {
            float v[4];
#pragma unroll
            for (int r = 0; r < 4; r++) {
                int j = warp * 8 + g * 4 + r;
                const float4* wq = (const float4*)WQ + (size_t)(h * DK + j) * 64;
                float4 a = wq[lane], c = wq[lane + 32];
                v[r] = a.x * qa.x + a.y * qa.y + a.z * qa.z + a.w * qa.w
                     + c.x * qb.x + c.y * qb.y + c.z * qb.z + c.w * qb.w;
            }
#pragma unroll
            for (int off = 16; off > 0; off >>= 1) {
#pragma unroll
                for (int r = 0; r < 4; r++) v[r] += __shfl_xor_sync(0xffffffffu, v[r], off);
            }
            if (lane < 4) qgh[warp * 8 + g * 4 + lane] = v[lane];
        }
        __syncthreads();
        float acc = 0.f;
#pragma unroll 16
        for (int j = 0; j < DK; j++) acc += qgh[j] * WK[(size_t)(h * DK + j) * D + t];
        d_qW[(b * H + h) * D + t] = acc * 0.125f;
    } else {
        // scan: bucket edges whose dst is a global node (smem hash of glob ids)
        __shared__ int hk[256];
        __shared__ int hv[256];
        hk[t] = -1;
        __syncthreads();
        if (t < bn) {
            int g = glob[t];
            unsigned slot = ((unsigned)g * 2654435761u) >> 24;
            for (;;) {
                int prev = atomicCAS(&hk[slot & 255], -1, g);
                if (prev == -1) { hv[slot & 255] = t; break; }
                if (prev == g) break;
                slot++;
            }
        }
        __syncthreads();

        int sb = bid - bn * H;
        int base = (sb * 256 + t) * 4;
        if (base >= ne) return;
        int ds[4];
        if (base + 4 <= ne) {
            int4 dv = *(const int4*)(dst + base);
            ds[0] = dv.x; ds[1] = dv.y; ds[2] = dv.z; ds[3] = dv.w;
        } else {
            for (int k = 0; k < 4; k++) ds[k] = (base + k < ne) ? dst[base + k] : -1;
        }
#pragma unroll
        for (int k = 0; k < 4; k++) {
            int g = ds[k];
            if (g < 0) continue;
            unsigned slot = ((unsigned)g * 2654435761u) >> 24;
            int bf = -1;
            for (;;) {
                int kk = hk[slot & 255];
                if (kk == -1) break;
                if (kk == g) { bf = hv[slot & 255]; break; }
                slot++;
            }
            if (bf >= 0) {
                int pos = atomicAdd(&d_bcnt[bf], 1);
                if (pos < BCAP) d_bsrc[bf * BCAP + pos] = src[base + k];
            }
        }
    }
}

// ============ K2: per-b scores + softmax + aggregation -> d_ax. grid bn. ============
__global__ void k_attn(const float* __restrict__ x, float* __restrict__ out) {
    __shared__ float4 qW4[H * 64];        // 4 KB
    __shared__ int    slist[SC_CAP];      // 1 KB
    __shared__ float  sc[SC_CAP * H];     // 4 KB
    int b = blockIdx.x, t = threadIdx.x;
    int lane = t & 31, warp = t >> 5;
    const float4* x4 = (const float4*)x;

    qW4[t] = ((const float4*)d_qW)[b * 256 + t];
    int n = d_bcnt[b];
    if (n > SC_CAP) n = SC_CAP;
    for (int i = t; i < n; i += 256) slist[i] = d_bsrc[b * BCAP + i];
    out[b * D + t] = 0.f;                 // zero output for k_epi's atomics
    __syncthreads();

    // Phase A: warp-per-edge scores (x rows land in L1 for Phase C reuse)
    for (int base = 0; base < n; base += 8) {
        int i = base + warp;
        if (i < n) {
            int s = slist[i];
            float4 xa = x4[(size_t)s * 64 + lane];
            float4 xb = x4[(size_t)s * 64 + 32 + lane];
            float v[H];
#pragma unroll
            for (int h = 0; h < H; h++) {
                float4 qa = qW4[h * 64 + lane], qb = qW4[h * 64 + 32 + lane];
                v[h] = xa.x * qa.x + xa.y * qa.y + xa.z * qa.z + xa.w * qa.w
                     + xb.x * qb.x + xb.y * qb.y + xb.z * qb.z + xb.w * qb.w;
            }
#pragma unroll
            for (int off = 16; off > 0; off >>= 1) {
#pragma unroll
                for (int h = 0; h < H; h++) v[h] += __shfl_xor_sync(0xffffffffu, v[h], off);
            }
            if (lane < H) sc[i * H + lane] = v[lane];
        }
    }
    __syncthreads();

    // Phase B: warp-per-head softmax
    if (warp < H) {
        int h = warp;
        float m = -3.4e38f;
        for (int i = lane; i < n; i += 32) m = fmaxf(m, sc[i * H + h]);
#pragma unroll
        for (int off = 16; off > 0; off >>= 1)
            m = fmaxf(m, __shfl_xor_sync(0xffffffffu, m, off));
        float sum = 0.f;
        for (int i = lane; i < n; i += 32) sum += __expf(sc[i * H + h] - m);
#pragma unroll
        for (int off = 16; off > 0; off >>= 1)
            sum += __shfl_xor_sync(0xffffffffu, sum, off);
        float inv = (sum > 0.f) ? 1.f / sum : 0.f;
        for (int i = lane; i < n; i += 32)
            sc[i * H + h] = __expf(sc[i * H + h] - m) * inv;
    }
    __syncthreads();

    // Phase C: aggregation, thread t = dim d; write ax to global
    {
        float a0 = 0.f, a1 = 0.f, a2 = 0.f, a3 = 0.f;
#pragma unroll 4
        for (int i = 0; i < n; i++) {
            float xv = x[(size_t)slist[i] * D + t];
            a0 += sc[i * H + 0] * xv;
            a1 += sc[i * H + 1] * xv;
            a2 += sc[i * H + 2] * xv;
            a3 += sc[i * H + 3] * xv;
        }
        float* axb = d_ax + b * H * D;
        axb[0 * D + t] = a0; axb[1 * D + t] = a1;
        axb[2 * D + t] = a2; axb[3 * D + t] = a3;
    }

    if (t == 0) d_bcnt[b] = 0;            // reset for next call
}

// ============ K3: epilogue. grid (bn, H). block (b,q): mid quarter + partial out ============
// Quarter q of mid rows [64q, 64q+64) lies entirely in head q, so only ax[b,q,:] is needed.
__global__ void k_epi(const float* __restrict__ WV,
                      const float* __restrict__ WO,
                      float* __restrict__ out) {
    __shared__ float axq[D];      // ax[b, q, :]
    __shared__ float midq[DK];    // mid quarter
    int b = blockIdx.x, q = blockIdx.y, t = threadIdx.x;
    int lane = t & 31, warp = t >> 5;

    axq[t] = d_ax[(b * H + q) * D + t];
    __syncthreads();

    // mid[64q + j] = WV[64q+j, :] . axq   — 8 warps x 8 rows, 4-row ILP batches
    float4 a0 = ((const float4*)axq)[lane];
    float4 a1 = ((const float4*)axq)[lane + 32];
#pragma unroll
    for (int g = 0; g < 2; g++) {
        float v[4];
#pragma unroll
        for (int r = 0; r < 4; r++) {
            int j = warp * 8 + g * 4 + r;
            const float4* wv = (const float4*)WV + (size_t)(q * DK + j) * 64;
            float4 w0 = wv[lane], w1 = wv[lane + 32];
            v[r] = w0.x * a0.x + w0.y * a0.y + w0.z * a0.z + w0.w * a0.w
                 + w1.x * a1.x + w1.y * a1.y + w1.z * a1.z + w1.w * a1.w;
        }
#pragma unroll
        for (int off = 16; off > 0; off >>= 1) {
#pragma unroll
            for (int r = 0; r < 4; r++) v[r] += __shfl_xor_sync(0xffffffffu, v[r], off);
        }
        if (lane < 4) midq[warp * 8 + g * 4 + lane] = v[lane];
    }
    __syncthreads();

    // partial out[b, t] += WO[t, 64q:64q+64] . midq  (thread-per-output-row)
    {
        const float4* wo = (const float4*)(WO + (size_t)t * D + q * DK);
        float acc = 0.f;
#pragma unroll
        for (int k = 0; k < 16; k++) {
            float4 w = wo[k];
            acc += w.x * midq[4 * k] + w.y * midq[4 * k + 1]
                 + w.z * midq[4 * k + 2] + w.w * midq[4 * k + 3];
        }
        atomicAdd(&out[b * D + t], acc);
    }
}

extern "C" void kernel_launch(void* const* d_in, const int* in_sizes, int n_in,
                              void* d_out, int out_size) {
    const float* query = (const float*)d_in[0];
    const float* x     = (const float*)d_in[1];
    const float* WQ    = (const float*)d_in[2];
    const float* WK    = (const float*)d_in[3];
    const float* WV    = (const float*)d_in[4];
    const float* WO    = (const float*)d_in[5];
    const int*   src   = (const int*)d_in[6];   // JAX x64 disabled: stored as int32
    const int*   dst   = (const int*)d_in[7];
    const int*   glob  = (const int*)d_in[8];

    int bn = in_sizes[8];              // 64
    if (bn > B_CAP) bn = B_CAP;
    int ne = in_sizes[6];              // 320000

    int scan_blocks = (ne + 4 * 256 - 1) / (4 * 256);   // 313
    k_front<<<bn * H + scan_blocks, 256>>>(query, WQ, WK, dst, src, glob, bn, ne);
    k_attn<<<bn, 256>>>(x, (float*)d_out);
    dim3 ge(bn, H);
    k_epi<<<ge, 256>>>(WV, WO, (float*)d_out);
}